// round 2
// baseline (speedup 1.0000x reference)
#include <cuda_runtime.h>
#include <math.h>

#define NN 100000          // nodes
#define NE 1600000         // edges (without self loops)
#define C  128             // in/hid channels
#define OC 64              // out channels
#define NG 64              // graphs

// ---------------- static device scratch ------------------------------------
__device__ float g_bufA[(size_t)NN * C];
__device__ float g_bufB[(size_t)NN * C];
__device__ int   g_col[NE];                // CSR column indices (src per dst)
__device__ int   g_cnt[NN];                // in-degree (without self loop)
__device__ int   g_rowptr[NN];             // CSR row start
__device__ int   g_fillptr[NN];            // atomic fill cursor
__device__ float g_dinv[NN];               // deg^-1/2 (deg includes self loop)
__device__ int   g_bsum[128];
__device__ int   g_gcnt[NG];
__device__ int   g_goff[NG + 1];
__device__ float g_pool[NG * C];
__device__ int   g_is64;                   // edge/batch index dtype flag

// ---------------- kernels ---------------------------------------------------

// idx 0: zero counters + detect index dtype (int64 high words are zero)
__global__ void k_prep(const int* e32, int N) {
    int tid = blockIdx.x * blockDim.x + threadIdx.x;
    int stride = gridDim.x * blockDim.x;
    for (int i = tid; i < N; i += stride) g_cnt[i] = 0;
    if (tid < NG) g_gcnt[tid] = 0;
    if (tid == 0) {
        int is64 = 1;
        #pragma unroll
        for (int i = 0; i < 8; i++) if (e32[2 * i + 1] != 0) is64 = 0;
        g_is64 = is64;
    }
}

// idx 1: in-degree histogram straight from the input edge buffer
__global__ void k_hist(const void* ei, int E) {
    int tid = blockIdx.x * blockDim.x + threadIdx.x;
    int stride = gridDim.x * blockDim.x;
    if (g_is64) {
        const long long* e = (const long long*)ei;
        for (int i = tid; i < E; i += stride)
            atomicAdd(&g_cnt[(int)e[(size_t)E + i]], 1);
    } else {
        const int* e = (const int*)ei;
        for (int i = tid; i < E; i += stride)
            atomicAdd(&g_cnt[e[E + i]], 1);
    }
}

// idx 2: per-graph node counts from batch
__global__ void k_ghist(const void* bat, int N) {
    int tid = blockIdx.x * blockDim.x + threadIdx.x;
    int stride = gridDim.x * blockDim.x;
    if (g_is64) {
        const long long* b = (const long long*)bat;
        for (int i = tid; i < N; i += stride) atomicAdd(&g_gcnt[(int)b[i]], 1);
    } else {
        const int* b = (const int*)bat;
        for (int i = tid; i < N; i += stride) atomicAdd(&g_gcnt[b[i]], 1);
    }
}

// idx 3 (PROFILED): Y = X @ W   X:[n,128] W:[128,128], no scaling
__global__ __launch_bounds__(256, 2) void k_gemm(
    const float* __restrict__ X, const float* __restrict__ W,
    float* __restrict__ Y, int n)
{
    __shared__ float Ws[C * C];      // 64 KB
    __shared__ float Xs[64 * C];     // 32 KB
    int tid = threadIdx.x;
    int row0 = blockIdx.x * 64;

    for (int i = tid; i < C * C; i += 256) Ws[i] = W[i];
    for (int i = tid; i < 64 * C; i += 256) {
        int r = row0 + (i >> 7);
        Xs[i] = (r < n) ? X[(size_t)r * C + (i & 127)] : 0.0f;
    }
    __syncthreads();

    int tn = tid & 31;    // cols [tn*4, tn*4+4)
    int tm = tid >> 5;    // rows [tm*8, tm*8+8) within tile
    float acc[8][4];
    #pragma unroll
    for (int r = 0; r < 8; r++)
        #pragma unroll
        for (int c = 0; c < 4; c++) acc[r][c] = 0.0f;

    #pragma unroll 4
    for (int k = 0; k < C; k++) {
        float4 wv = *(const float4*)&Ws[k * C + tn * 4];
        #pragma unroll
        for (int r = 0; r < 8; r++) {
            float xv = Xs[(tm * 8 + r) * C + k];
            acc[r][0] += xv * wv.x;
            acc[r][1] += xv * wv.y;
            acc[r][2] += xv * wv.z;
            acc[r][3] += xv * wv.w;
        }
    }

    #pragma unroll
    for (int r = 0; r < 8; r++) {
        int row = row0 + tm * 8 + r;
        if (row < n) {
            *(float4*)&Y[(size_t)row * C + tn * 4] =
                make_float4(acc[r][0], acc[r][1], acc[r][2], acc[r][3]);
        }
    }
}

// idx 4: block-wide exclusive scan of g_cnt + compute dinv
__global__ void k_scan1(int n) {
    __shared__ int sh[1024];
    int i = blockIdx.x * 1024 + threadIdx.x;
    int v = (i < n) ? g_cnt[i] : 0;
    sh[threadIdx.x] = v;
    __syncthreads();
    for (int off = 1; off < 1024; off <<= 1) {
        int t = (threadIdx.x >= off) ? sh[threadIdx.x - off] : 0;
        __syncthreads();
        sh[threadIdx.x] += t;
        __syncthreads();
    }
    if (i < n) {
        g_rowptr[i] = sh[threadIdx.x] - v;          // exclusive
        g_dinv[i] = rsqrtf((float)(v + 1));         // +1 self loop
    }
    if (threadIdx.x == 1023) g_bsum[blockIdx.x] = sh[1023];
}

// idx 5
__global__ void k_scan2(int nb) {
    __shared__ int sh[128];
    int v = (threadIdx.x < nb) ? g_bsum[threadIdx.x] : 0;
    sh[threadIdx.x] = v;
    __syncthreads();
    for (int off = 1; off < 128; off <<= 1) {
        int t = (threadIdx.x >= off) ? sh[threadIdx.x - off] : 0;
        __syncthreads();
        sh[threadIdx.x] += t;
        __syncthreads();
    }
    if (threadIdx.x < nb) g_bsum[threadIdx.x] = sh[threadIdx.x] - v;
}

// idx 6
__global__ void k_scan3(int n) {
    int i = blockIdx.x * blockDim.x + threadIdx.x;
    if (i < n) {
        int r = g_rowptr[i] + g_bsum[i >> 10];
        g_rowptr[i] = r;
        g_fillptr[i] = r;
    }
}

// idx 7: scatter CSR columns straight from the input edge buffer
__global__ void k_fill(const void* ei, int E) {
    int tid = blockIdx.x * blockDim.x + threadIdx.x;
    int stride = gridDim.x * blockDim.x;
    if (g_is64) {
        const long long* e = (const long long*)ei;
        for (int i = tid; i < E; i += stride) {
            int d = (int)e[(size_t)E + i];
            int s = (int)e[i];
            int p = atomicAdd(&g_fillptr[d], 1);
            g_col[p] = s;
        }
    } else {
        const int* e = (const int*)ei;
        for (int i = tid; i < E; i += stride) {
            int d = e[E + i];
            int s = e[i];
            int p = atomicAdd(&g_fillptr[d], 1);
            g_col[p] = s;
        }
    }
}

// idx 8/10: h[i] = relu(dinv_i * (dinv_i*y_i + sum_s dinv_s*y_s) + b)
// warp per node, lane owns 4 channels (float4)
__global__ __launch_bounds__(256) void k_agg(
    const float* __restrict__ Yin, const float* __restrict__ bias,
    float* __restrict__ Hout, int n)
{
    int node = (blockIdx.x * blockDim.x + threadIdx.x) >> 5;
    int lane = threadIdx.x & 31;
    if (node >= n) return;

    const float4* Y4 = (const float4*)Yin;
    float di = g_dinv[node];
    float4 s4 = Y4[(size_t)node * 32 + lane];
    float4 acc = make_float4(s4.x * di, s4.y * di, s4.z * di, s4.w * di);

    int e = g_rowptr[node];
    int end = e + g_cnt[node];

    for (; e + 4 <= end; e += 4) {
        int s0 = g_col[e],     s1 = g_col[e + 1];
        int s2 = g_col[e + 2], s3 = g_col[e + 3];
        float w0 = g_dinv[s0], w1 = g_dinv[s1];
        float w2 = g_dinv[s2], w3 = g_dinv[s3];
        float4 a = Y4[(size_t)s0 * 32 + lane];
        float4 b = Y4[(size_t)s1 * 32 + lane];
        float4 c = Y4[(size_t)s2 * 32 + lane];
        float4 d = Y4[(size_t)s3 * 32 + lane];
        acc.x += w0 * a.x + w1 * b.x + w2 * c.x + w3 * d.x;
        acc.y += w0 * a.y + w1 * b.y + w2 * c.y + w3 * d.y;
        acc.z += w0 * a.z + w1 * b.z + w2 * c.z + w3 * d.z;
        acc.w += w0 * a.w + w1 * b.w + w2 * c.w + w3 * d.w;
    }
    for (; e < end; e++) {
        int s = g_col[e];
        float w = g_dinv[s];
        float4 a = Y4[(size_t)s * 32 + lane];
        acc.x += w * a.x; acc.y += w * a.y;
        acc.z += w * a.z; acc.w += w * a.w;
    }

    float4 bv = ((const float4*)bias)[lane];
    float4 o;
    o.x = fmaxf(di * acc.x + bv.x, 0.0f);
    o.y = fmaxf(di * acc.y + bv.y, 0.0f);
    o.z = fmaxf(di * acc.z + bv.z, 0.0f);
    o.w = fmaxf(di * acc.w + bv.w, 0.0f);
    ((float4*)Hout)[(size_t)node * 32 + lane] = o;
}

// idx 11
__global__ void k_goff() {
    if (threadIdx.x == 0) {
        int s = 0;
        for (int g = 0; g < NG; g++) { g_goff[g] = s; s += g_gcnt[g]; }
        g_goff[NG] = s;
    }
}

// idx 12: one block per graph, one thread per channel
__global__ void k_pool(const float* __restrict__ H) {
    int g = blockIdx.x;
    int c = threadIdx.x;
    int s = g_goff[g], e = g_goff[g + 1];
    float acc = 0.0f;
    int r = s;
    for (; r + 4 <= e; r += 4) {
        acc += H[(size_t)r * C + c] + H[(size_t)(r + 1) * C + c]
             + H[(size_t)(r + 2) * C + c] + H[(size_t)(r + 3) * C + c];
    }
    for (; r < e; r++) acc += H[(size_t)r * C + c];
    float cnt = (float)(e - s);
    g_pool[g * C + c] = acc / fmaxf(cnt, 1.0f);
}

// idx 13
__global__ void k_head(const float* __restrict__ Wl,
                       const float* __restrict__ bl,
                       float* __restrict__ out)
{
    int g = blockIdx.x;
    int o = threadIdx.x;
    float acc = bl[o];
    #pragma unroll 4
    for (int k = 0; k < C; k++) acc += g_pool[g * C + k] * Wl[k * OC + o];
    out[g * OC + o] = acc;
}

// ---------------- launch -----------------------------------------------------
extern "C" void kernel_launch(void* const* d_in, const int* in_sizes, int n_in,
                              void* d_out, int out_size) {
    const float* x   = (const float*)d_in[0];
    const void*  ei  = d_in[1];
    const void*  bat = d_in[2];
    const float* W1  = (const float*)d_in[3];
    const float* b1  = (const float*)d_in[4];
    const float* W2  = (const float*)d_in[5];
    const float* b2  = (const float*)d_in[6];
    const float* Wl  = (const float*)d_in[7];
    const float* bl  = (const float*)d_in[8];
    float* out = (float*)d_out;

    int N = in_sizes[0] / C;        // 100000
    int E = in_sizes[1] / 2;        // 1600000
    int nb = (N + 1023) / 1024;

    k_prep <<<256, 256>>>((const int*)ei, N);                 // 0
    k_hist <<<1024, 256>>>(ei, E);                            // 1
    k_ghist<<<256, 256>>>(bat, N);                            // 2
    k_gemm <<<(N + 63) / 64, 256>>>(x, W1, g_bufA, N);        // 3  <-- profiled
    k_scan1<<<nb, 1024>>>(N);                                 // 4
    k_scan2<<<1, 128>>>(nb);                                  // 5
    k_scan3<<<(N + 255) / 256, 256>>>(N);                     // 6
    k_fill <<<1024, 256>>>(ei, E);                            // 7
    k_agg  <<<(N * 32 + 255) / 256, 256>>>(g_bufA, b1, g_bufB, N);  // 8
    k_gemm <<<(N + 63) / 64, 256>>>(g_bufB, W2, g_bufA, N);   // 9
    k_agg  <<<(N * 32 + 255) / 256, 256>>>(g_bufA, b2, g_bufB, N);  // 10
    k_goff <<<1, 32>>>();                                     // 11
    k_pool <<<NG, C>>>(g_bufB);                               // 12
    k_head <<<NG, OC>>>(Wl, bl, out);                         // 13
}